// round 17
// baseline (speedup 1.0000x reference)
#include <cuda_runtime.h>
#include <cuda_bf16.h>

// Problem constants (fixed by the reference).
#define N_  512
#define L_  5
#define H_  8
#define D_  16
#define E_  10000

#define THREADS_G     256
#define PAIRS_PER_BLK 256
#define PP_           2
#define NPROJ_BLOCKS  40                                   // 40*256 >= E
#define NGATH_BLOCKS  ((N_ * N_) / PAIRS_PER_BLK)          // 1024
#define GRID_TOTAL    (NPROJ_BLOCKS + NGATH_BLOCKS)        // 1064 (< 1184 resident)

// Scratch: projected edge table P[e][l][h] = dot(edge_features[e], W[1+l][h]).
// 400,000 floats = 1.6 MB (L2-resident). Chunk (e,l) = 32 B at byte offset
// e*160 + l*32; 160 ≡ 32 (mod 128) -> every chunk sits inside ONE 128B line.
__device__ float g_P[E_ * L_ * H_];

// Device-side dependency barrier (reset by the last exiting block each launch
// -> deterministic across graph replays).
__device__ unsigned g_done = 0;   // projection blocks completed
__device__ unsigned g_exit = 0;   // blocks fully finished

// ---------------------------------------------------------------------------
// Fused kernel, role-split:
//   blocks 0..39      : projection only (R7 shape, W in smem, unroll-1 l loop)
//   blocks 40..1063   : index staging -> spin on g_done -> R10 gather
// __launch_bounds__(256, 8) caps regs at 32 -> 8 blocks/SM -> all 1064 blocks
// are wave-1 resident (1184 slots); projection blocks cannot be starved.
// ---------------------------------------------------------------------------
__global__ void __launch_bounds__(THREADS_G, 8)
fused_kernel(const float* __restrict__ F,    // [E, D]
             const float* __restrict__ W,    // [L+1, H*D]
             const int*   __restrict__ spe,  // [N, N, L] int32
             float*       __restrict__ out)  // [H, N, N]
{
    __shared__ int   s_idx[PAIRS_PER_BLK * L_];        // 1280 ints  (gather)
    __shared__ float s_out[H_ * (PAIRS_PER_BLK + 1)];  // 2056 floats (gather
                                                       //  out / proj sW)
    const int b   = blockIdx.x;
    const int tid = threadIdx.x;

    if (b < NPROJ_BLOCKS) {
        // ================= Phase A: projection =================
        float* sW = s_out;                    // reuse: 640 floats needed
        for (int i = tid; i < L_ * H_ * D_; i += THREADS_G)
            sW[i] = W[H_ * D_ + i];           // rows 1..L (skip row 0)
        __syncthreads();

        int e = b * THREADS_G + tid;
        if (e < E_) {
            const float4* fp = reinterpret_cast<const float4*>(F + (size_t)e * D_);
            float4 f0 = fp[0], f1 = fp[1], f2 = fp[2], f3 = fp[3];
            float fr[D_] = { f0.x, f0.y, f0.z, f0.w,
                             f1.x, f1.y, f1.z, f1.w,
                             f2.x, f2.y, f2.z, f2.w,
                             f3.x, f3.y, f3.z, f3.w };

            // unroll-1 over l keeps live state ~32 regs (acc[8] + fr[16]).
            #pragma unroll 1
            for (int l = 0; l < L_; ++l) {
                float acc[H_];
                #pragma unroll
                for (int h = 0; h < H_; ++h) {
                    float s = 0.0f;
                    const float* w = &sW[(l * H_ + h) * D_];
                    #pragma unroll
                    for (int d = 0; d < D_; ++d)
                        s = fmaf(fr[d], w[d], s);
                    acc[h] = s;
                }
                float4* dst = reinterpret_cast<float4*>(
                    g_P + (size_t)e * (L_ * H_) + l * H_);
                float4 v0 = { acc[0], acc[1], acc[2], acc[3] };
                float4 v1 = { acc[4], acc[5], acc[6], acc[7] };
                dst[0] = v0;
                dst[1] = v1;
            }
        }
        __syncthreads();                      // all P stores of block issued
        __threadfence();                      // release to device scope
        if (tid == 0) atomicAdd(&g_done, 1u);
    } else {
        // ================= Phase B: gather =================
        const int base = (b - NPROJ_BLOCKS) * PAIRS_PER_BLK;

        // Coalesced index staging (independent of g_P) — overlaps phase A.
        const int4* g4 = reinterpret_cast<const int4*>(spe + (size_t)base * L_);
        #pragma unroll
        for (int i = tid; i < (PAIRS_PER_BLK * L_) / 4; i += THREADS_G)
            reinterpret_cast<int4*>(s_idx)[i] = g4[i];

        // Wait for projection (acquire).
        if (tid == 0) {
            while (*(volatile unsigned*)&g_done < NPROJ_BLOCKS)
                __nanosleep(20);
            __threadfence();
        }
        __syncthreads();                      // also closes staging loop

        const int pair = tid >> 1;            // 0..127
        const int c    = tid & 1;
        const int coff = c * 4;

        float a[PP_][4];
        float cntf[PP_];
        #pragma unroll
        for (int pp = 0; pp < PP_; ++pp) {
            a[pp][0] = a[pp][1] = a[pp][2] = a[pp][3] = 0.f;
            cntf[pp] = 0.f;
        }

        #pragma unroll
        for (int pp = 0; pp < PP_; ++pp) {
            const int pr = pair + pp * 128;
            #pragma unroll
            for (int l = 0; l < L_; ++l) {
                int e = s_idx[pr * L_ + l];
                bool valid = (unsigned)e < (unsigned)E_;
                int  ei    = valid ? e : 0;
                float m    = valid ? 1.0f : 0.0f;
                const float4 v = *reinterpret_cast<const float4*>(
                    g_P + (size_t)ei * (L_ * H_) + l * H_ + coff);
                a[pp][0] = fmaf(m, v.x, a[pp][0]);
                a[pp][1] = fmaf(m, v.y, a[pp][1]);
                a[pp][2] = fmaf(m, v.z, a[pp][2]);
                a[pp][3] = fmaf(m, v.w, a[pp][3]);
                cntf[pp] += m;
            }
        }

        #pragma unroll
        for (int pp = 0; pp < PP_; ++pp) {
            const int pr  = pair + pp * 128;
            float inv = 1.0f / fmaxf(cntf[pp], 1.0f);
            s_out[(coff + 0) * (PAIRS_PER_BLK + 1) + pr] = a[pp][0] * inv;
            s_out[(coff + 1) * (PAIRS_PER_BLK + 1) + pr] = a[pp][1] * inv;
            s_out[(coff + 2) * (PAIRS_PER_BLK + 1) + pr] = a[pp][2] * inv;
            s_out[(coff + 3) * (PAIRS_PER_BLK + 1) + pr] = a[pp][3] * inv;
        }
        __syncthreads();

        // 8 planes x 256 pairs, fully coalesced.
        const int NN = N_ * N_;
        #pragma unroll
        for (int k = 0; k < (H_ * PAIRS_PER_BLK) / THREADS_G; ++k) {
            int i = k * THREADS_G + tid;
            int h = i >> 8;
            int j = i & 255;
            out[h * NN + base + j] = s_out[h * (PAIRS_PER_BLK + 1) + j];
        }
        __syncthreads();
    }

    // Replay-safe reset: last exiting block (necessarily a gather block)
    // zeroes the barrier state for the next graph replay.
    if (tid == 0) {
        unsigned n = atomicAdd(&g_exit, 1u);
        if (n == GRID_TOTAL - 1) {
            atomicExch(&g_done, 0u);
            atomicExch(&g_exit, 0u);
        }
    }
}

// ---------------------------------------------------------------------------
// Launch: inputs in metadata order:
//   d_in[0] = edge_features_s      float32 [E*D]
//   d_in[1] = edge_weights         float32 [(L+1)*H*D]
//   d_in[2] = shortest_path_edges  int32   [N*N*L]
// d_out = float32 [H*N*N]
// ---------------------------------------------------------------------------
extern "C" void kernel_launch(void* const* d_in, const int* in_sizes, int n_in,
                              void* d_out, int out_size)
{
    const float* F   = (const float*)d_in[0];
    const float* W   = (const float*)d_in[1];
    const int*   spe = (const int*)d_in[2];
    float*       out = (float*)d_out;

    fused_kernel<<<GRID_TOTAL, THREADS_G>>>(F, W, spe, out);
}